// round 2
// baseline (speedup 1.0000x reference)
#include <cuda_runtime.h>
#include <cuda_bf16.h>
#include <cstdint>

#define NN 100000
#define NE 1600000
#define NG 50
#define FD 128

// Scratch (allocation-free rule: __device__ globals)
__device__ float g_agg_in[(size_t)NN * FD];
__device__ float g_agg_out[(size_t)NN * FD];
__device__ float g_gp[NG * FD];

// ---------------------------------------------------------------------------
// Zero the aggregation buffers (102 MB of writes)
// ---------------------------------------------------------------------------
__global__ void zero_kernel() {
    size_t i = (size_t)blockIdx.x * blockDim.x + threadIdx.x;
    size_t n4 = (size_t)NN * FD / 4;
    if (i < n4) {
        ((float4*)g_agg_in)[i]  = make_float4(0.f, 0.f, 0.f, 0.f);
        ((float4*)g_agg_out)[i] = make_float4(0.f, 0.f, 0.f, 0.f);
    }
}

// ---------------------------------------------------------------------------
// One-pass scatter: each warp owns one edge row (128 floats = 512B, fully
// coalesced), red.global.add.v4.f32 into both receiver and sender agg rows.
// ---------------------------------------------------------------------------
__global__ void scatter_kernel(const float* __restrict__ ef,
                               const int* __restrict__ recv,
                               const int* __restrict__ send) {
    int e    = (int)((blockIdx.x * blockDim.x + threadIdx.x) >> 5);
    int lane = threadIdx.x & 31;
    if (e >= NE) return;
    int r = __ldg(recv + e);
    int s = __ldg(send + e);
    float4 v = ((const float4*)(ef + (size_t)e * FD))[lane];
    float* pin  = g_agg_in  + (size_t)r * FD + lane * 4;
    float* pout = g_agg_out + (size_t)s * FD + lane * 4;
    asm volatile("red.global.add.v4.f32 [%0], {%1,%2,%3,%4};"
                 :: "l"(pin),  "f"(v.x), "f"(v.y), "f"(v.z), "f"(v.w) : "memory");
    asm volatile("red.global.add.v4.f32 [%0], {%1,%2,%3,%4};"
                 :: "l"(pout), "f"(v.x), "f"(v.y), "f"(v.z), "f"(v.w) : "memory");
}

// ---------------------------------------------------------------------------
// gp[g][n] = bias[n] + sum_k glob[g][k] * Wg[n][k]   (tiny: 50x128)
// ---------------------------------------------------------------------------
__global__ void globproj_kernel(const float* __restrict__ gf,
                                const float* __restrict__ Wg,
                                const float* __restrict__ bias) {
    __shared__ float gs[FD];
    int g = blockIdx.x;
    int n = threadIdx.x;
    gs[n] = gf[g * FD + n];
    __syncthreads();
    float acc = __ldg(bias + n);
    const float* wrow = Wg + (size_t)n * FD;
    #pragma unroll 8
    for (int k = 0; k < FD; k++) acc = fmaf(gs[k], __ldg(wrow + k), acc);
    g_gp[g * FD + n] = acc;
}

// ---------------------------------------------------------------------------
// Fused GEMM: out[m][n] = sum over 3 segments of X_seg[m][:] . W_seg[n][:]
//                         + gp[graph_idx[m]][n]
// Tile 128x128, 256 threads, 8x8 per-thread micro-tile, accumulators packed
// as f32x2 and driven with fma.rn.f32x2 (2 FMA/inst, FFMA2 path).
// ---------------------------------------------------------------------------
__global__ void __launch_bounds__(256, 2)
gemm_kernel(const float* __restrict__ node,
            const float* __restrict__ Wn,
            const float* __restrict__ Wi,
            const float* __restrict__ Wo,
            const int* __restrict__ gidx,
            float* __restrict__ out) {
    __shared__ float Xs[8][FD];   // [k][m]
    __shared__ float Ws[8][FD];   // [k][n]

    const int tid  = threadIdx.x;
    const int ty   = tid >> 4;        // 0..15  -> row group
    const int tx   = tid & 15;        // 0..15  -> col group
    const int m0   = blockIdx.x * 128;
    const int lrow = tid >> 1;        // 0..127 (load row / load n)
    const int lk   = (tid & 1) * 4;   // 0 or 4

    unsigned long long acc[8][4];
    #pragma unroll
    for (int i = 0; i < 8; i++)
        #pragma unroll
        for (int j = 0; j < 4; j++) acc[i][j] = 0ULL;  // (0.f,0.f)

    #pragma unroll
    for (int seg = 0; seg < 3; seg++) {
        const float* X = (seg == 0) ? node : (seg == 1) ? g_agg_in : g_agg_out;
        const float* W = (seg == 0) ? Wn   : (seg == 1) ? Wi       : Wo;
        for (int kb = 0; kb < 16; kb++) {
            const int k0 = kb * 8;
            // stage X (transposed) and W (transposed) tiles
            float4 xv = make_float4(0.f, 0.f, 0.f, 0.f);
            const int gm = m0 + lrow;
            if (gm < NN) xv = *(const float4*)(X + (size_t)gm * FD + k0 + lk);
            float4 wv = *(const float4*)(W + (size_t)lrow * FD + k0 + lk);
            __syncthreads();
            Xs[lk + 0][lrow] = xv.x; Xs[lk + 1][lrow] = xv.y;
            Xs[lk + 2][lrow] = xv.z; Xs[lk + 3][lrow] = xv.w;
            Ws[lk + 0][lrow] = wv.x; Ws[lk + 1][lrow] = wv.y;
            Ws[lk + 2][lrow] = wv.z; Ws[lk + 3][lrow] = wv.w;
            __syncthreads();

            #pragma unroll
            for (int kk = 0; kk < 8; kk++) {
                float4 a0 = *(const float4*)&Xs[kk][ty * 8];
                float4 a1 = *(const float4*)&Xs[kk][ty * 8 + 4];
                const unsigned long long* wp =
                    (const unsigned long long*)&Ws[kk][tx * 8];
                unsigned long long w2[4];
                w2[0] = wp[0]; w2[1] = wp[1]; w2[2] = wp[2]; w2[3] = wp[3];
                float a[8] = {a0.x, a0.y, a0.z, a0.w, a1.x, a1.y, a1.z, a1.w};
                #pragma unroll
                for (int i = 0; i < 8; i++) {
                    unsigned long long a2;
                    asm("mov.b64 %0, {%1, %1};" : "=l"(a2) : "f"(a[i]));
                    #pragma unroll
                    for (int j = 0; j < 4; j++)
                        asm("fma.rn.f32x2 %0, %1, %2, %0;"
                            : "+l"(acc[i][j]) : "l"(a2), "l"(w2[j]));
                }
            }
        }
    }

    // epilogue: + gp[graph_idx[m]] (bias folded in), fully overwrite out
    #pragma unroll
    for (int i = 0; i < 8; i++) {
        const int m = m0 + ty * 8 + i;
        if (m < NN) {
            const int g = __ldg(gidx + m);
            const float4* gpp = (const float4*)(g_gp + (size_t)g * FD + tx * 8);
            float4 b0 = gpp[0], b1 = gpp[1];
            float r[8];
            #pragma unroll
            for (int j = 0; j < 4; j++) {
                float lo, hi;
                asm("mov.b64 {%0, %1}, %2;" : "=f"(lo), "=f"(hi) : "l"(acc[i][j]));
                r[2 * j]     = lo;
                r[2 * j + 1] = hi;
            }
            float4 o0 = make_float4(r[0] + b0.x, r[1] + b0.y, r[2] + b0.z, r[3] + b0.w);
            float4 o1 = make_float4(r[4] + b1.x, r[5] + b1.y, r[6] + b1.z, r[7] + b1.w);
            float* op = out + (size_t)m * FD + tx * 8;
            *(float4*)(op)     = o0;
            *(float4*)(op + 4) = o1;
        }
    }
}

// ---------------------------------------------------------------------------
extern "C" void kernel_launch(void* const* d_in, const int* in_sizes, int n_in,
                              void* d_out, int out_size) {
    const float* node = (const float*)d_in[0];
    const float* edge = (const float*)d_in[1];
    const float* glob = (const float*)d_in[2];
    const float* Wn   = (const float*)d_in[3];
    const float* Wi   = (const float*)d_in[4];
    const float* Wo   = (const float*)d_in[5];
    const float* Wg   = (const float*)d_in[6];
    const float* bias = (const float*)d_in[7];
    const int* recv   = (const int*)d_in[8];
    const int* send   = (const int*)d_in[9];
    const int* gidx   = (const int*)d_in[10];
    float* out        = (float*)d_out;

    zero_kernel<<<((size_t)NN * FD / 4 + 255) / 256, 256>>>();
    scatter_kernel<<<NE / 8, 256>>>(edge, recv, send);        // 8 warps/block, 1 edge/warp
    globproj_kernel<<<NG, FD>>>(glob, Wg, bias);
    gemm_kernel<<<(NN + 127) / 128, 256>>>(node, Wn, Wi, Wo, gidx, out);
}

// round 3
// speedup vs baseline: 1.0008x; 1.0008x over previous
#include <cuda_runtime.h>
#include <cuda_bf16.h>
#include <cstdint>

#define NN 100000
#define NE 1600000
#define NG 50
#define FD 128

// Scratch (allocation-free rule: __device__ globals)
__device__ float g_agg_in[(size_t)NN * FD];
__device__ float g_agg_out[(size_t)NN * FD];
__device__ float g_gp[NG * FD];

// ---------------------------------------------------------------------------
// Zero the aggregation buffers (102 MB of writes)
// ---------------------------------------------------------------------------
__global__ void zero_kernel() {
    size_t i = (size_t)blockIdx.x * blockDim.x + threadIdx.x;
    size_t n4 = (size_t)NN * FD / 4;
    if (i < n4) {
        ((float4*)g_agg_in)[i]  = make_float4(0.f, 0.f, 0.f, 0.f);
        ((float4*)g_agg_out)[i] = make_float4(0.f, 0.f, 0.f, 0.f);
    }
}

// ---------------------------------------------------------------------------
// Scatter via TMA bulk reduction: each warp stages one 512B edge row in SMEM,
// then ONE lane issues cp.reduce.async.bulk (add.f32) into the receiver and
// sender aggregation rows. 2 bulk ops per edge instead of 64 REDG lane-ops.
// 4 edges per warp, 2-slot double buffer per warp.
// ---------------------------------------------------------------------------
#define EPW 4   // edges per warp

__device__ __forceinline__ uint32_t smem_u32(const void* p) {
    uint32_t a;
    asm("{ .reg .u64 t; cvta.to.shared.u64 t, %1; cvt.u32.u64 %0, t; }"
        : "=r"(a) : "l"(p));
    return a;
}

__global__ void __launch_bounds__(256)
scatter_kernel(const float* __restrict__ ef,
               const int* __restrict__ recv,
               const int* __restrict__ send) {
    __shared__ __align__(16) float buf[8][2][FD];   // 8 warps x 2 slots x 512B
    const int warp = threadIdx.x >> 5;
    const int lane = threadIdx.x & 31;
    const long long ebase = ((long long)blockIdx.x * 8 + warp) * EPW;

    uint32_t sslot[2];
    sslot[0] = smem_u32(&buf[warp][0][0]);
    sslot[1] = smem_u32(&buf[warp][1][0]);

    #pragma unroll
    for (int i = 0; i < EPW; i++) {
        long long e = ebase + i;
        if (e >= NE) break;
        const int slot = i & 1;

        // recycle slot: wait until the bulk group issued 2 iters ago has
        // finished READING its smem
        if (i >= 2) {
            if (lane == 0)
                asm volatile("cp.async.bulk.wait_group.read 1;" ::: "memory");
            __syncwarp();
        }

        // stage the 512B edge row (fully coalesced, 16B/lane)
        float4 v = ((const float4*)(ef + (size_t)e * FD))[lane];
        ((float4*)&buf[warp][slot][0])[lane] = v;
        __syncwarp();

        if (lane == 0) {
            const int r = __ldg(recv + e);
            const int s = __ldg(send + e);
            float* pin  = g_agg_in  + (size_t)r * FD;
            float* pout = g_agg_out + (size_t)s * FD;
            // order generic STS before async-proxy read
            asm volatile("fence.proxy.async.shared::cta;" ::: "memory");
            asm volatile(
                "cp.reduce.async.bulk.global.shared::cta.bulk_group.add.f32 "
                "[%0], [%1], %2;"
                :: "l"(pin), "r"(sslot[slot]), "n"(FD * 4) : "memory");
            asm volatile(
                "cp.reduce.async.bulk.global.shared::cta.bulk_group.add.f32 "
                "[%0], [%1], %2;"
                :: "l"(pout), "r"(sslot[slot]), "n"(FD * 4) : "memory");
            asm volatile("cp.async.bulk.commit_group;" ::: "memory");
        }
    }
    // make all reductions fully complete before kernel end (inter-kernel order)
    if (lane == 0)
        asm volatile("cp.async.bulk.wait_group 0;" ::: "memory");
}

// ---------------------------------------------------------------------------
// gp[g][n] = bias[n] + sum_k glob[g][k] * Wg[n][k]   (tiny: 50x128)
// ---------------------------------------------------------------------------
__global__ void globproj_kernel(const float* __restrict__ gf,
                                const float* __restrict__ Wg,
                                const float* __restrict__ bias) {
    __shared__ float gs[FD];
    int g = blockIdx.x;
    int n = threadIdx.x;
    gs[n] = gf[g * FD + n];
    __syncthreads();
    float acc = __ldg(bias + n);
    const float* wrow = Wg + (size_t)n * FD;
    #pragma unroll 8
    for (int k = 0; k < FD; k++) acc = fmaf(gs[k], __ldg(wrow + k), acc);
    g_gp[g * FD + n] = acc;
}

// ---------------------------------------------------------------------------
// Fused GEMM: out[m][n] = sum over 3 segments of X_seg[m][:] . W_seg[n][:]
//                         + gp[graph_idx[m]][n]
// (unchanged this round — tensor-core rewrite is the next lever)
// ---------------------------------------------------------------------------
__global__ void __launch_bounds__(256, 2)
gemm_kernel(const float* __restrict__ node,
            const float* __restrict__ Wn,
            const float* __restrict__ Wi,
            const float* __restrict__ Wo,
            const int* __restrict__ gidx,
            float* __restrict__ out) {
    __shared__ float Xs[8][FD];   // [k][m]
    __shared__ float Ws[8][FD];   // [k][n]

    const int tid  = threadIdx.x;
    const int ty   = tid >> 4;        // 0..15  -> row group
    const int tx   = tid & 15;        // 0..15  -> col group
    const int m0   = blockIdx.x * 128;
    const int lrow = tid >> 1;        // 0..127 (load row / load n)
    const int lk   = (tid & 1) * 4;   // 0 or 4

    unsigned long long acc[8][4];
    #pragma unroll
    for (int i = 0; i < 8; i++)
        #pragma unroll
        for (int j = 0; j < 4; j++) acc[i][j] = 0ULL;  // (0.f,0.f)

    #pragma unroll
    for (int seg = 0; seg < 3; seg++) {
        const float* X = (seg == 0) ? node : (seg == 1) ? g_agg_in : g_agg_out;
        const float* W = (seg == 0) ? Wn   : (seg == 1) ? Wi       : Wo;
        for (int kb = 0; kb < 16; kb++) {
            const int k0 = kb * 8;
            float4 xv = make_float4(0.f, 0.f, 0.f, 0.f);
            const int gm = m0 + lrow;
            if (gm < NN) xv = *(const float4*)(X + (size_t)gm * FD + k0 + lk);
            float4 wv = *(const float4*)(W + (size_t)lrow * FD + k0 + lk);
            __syncthreads();
            Xs[lk + 0][lrow] = xv.x; Xs[lk + 1][lrow] = xv.y;
            Xs[lk + 2][lrow] = xv.z; Xs[lk + 3][lrow] = xv.w;
            Ws[lk + 0][lrow] = wv.x; Ws[lk + 1][lrow] = wv.y;
            Ws[lk + 2][lrow] = wv.z; Ws[lk + 3][lrow] = wv.w;
            __syncthreads();

            #pragma unroll
            for (int kk = 0; kk < 8; kk++) {
                float4 a0 = *(const float4*)&Xs[kk][ty * 8];
                float4 a1 = *(const float4*)&Xs[kk][ty * 8 + 4];
                const unsigned long long* wp =
                    (const unsigned long long*)&Ws[kk][tx * 8];
                unsigned long long w2[4];
                w2[0] = wp[0]; w2[1] = wp[1]; w2[2] = wp[2]; w2[3] = wp[3];
                float a[8] = {a0.x, a0.y, a0.z, a0.w, a1.x, a1.y, a1.z, a1.w};
                #pragma unroll
                for (int i = 0; i < 8; i++) {
                    unsigned long long a2;
                    asm("mov.b64 %0, {%1, %1};" : "=l"(a2) : "f"(a[i]));
                    #pragma unroll
                    for (int j = 0; j < 4; j++)
                        asm("fma.rn.f32x2 %0, %1, %2, %0;"
                            : "+l"(acc[i][j]) : "l"(a2), "l"(w2[j]));
                }
            }
        }
    }

    // epilogue: + gp[graph_idx[m]] (bias folded in), fully overwrite out
    #pragma unroll
    for (int i = 0; i < 8; i++) {
        const int m = m0 + ty * 8 + i;
        if (m < NN) {
            const int g = __ldg(gidx + m);
            const float4* gpp = (const float4*)(g_gp + (size_t)g * FD + tx * 8);
            float4 b0 = gpp[0], b1 = gpp[1];
            float r[8];
            #pragma unroll
            for (int j = 0; j < 4; j++) {
                float lo, hi;
                asm("mov.b64 {%0, %1}, %2;" : "=f"(lo), "=f"(hi) : "l"(acc[i][j]));
                r[2 * j]     = lo;
                r[2 * j + 1] = hi;
            }
            float4 o0 = make_float4(r[0] + b0.x, r[1] + b0.y, r[2] + b0.z, r[3] + b0.w);
            float4 o1 = make_float4(r[4] + b1.x, r[5] + b1.y, r[6] + b1.z, r[7] + b1.w);
            float* op = out + (size_t)m * FD + tx * 8;
            *(float4*)(op)     = o0;
            *(float4*)(op + 4) = o1;
        }
    }
}

// ---------------------------------------------------------------------------
extern "C" void kernel_launch(void* const* d_in, const int* in_sizes, int n_in,
                              void* d_out, int out_size) {
    const float* node = (const float*)d_in[0];
    const float* edge = (const float*)d_in[1];
    const float* glob = (const float*)d_in[2];
    const float* Wn   = (const float*)d_in[3];
    const float* Wi   = (const float*)d_in[4];
    const float* Wo   = (const float*)d_in[5];
    const float* Wg   = (const float*)d_in[6];
    const float* bias = (const float*)d_in[7];
    const int* recv   = (const int*)d_in[8];
    const int* send   = (const int*)d_in[9];
    const int* gidx   = (const int*)d_in[10];
    float* out        = (float*)d_out;

    zero_kernel<<<((size_t)NN * FD / 4 + 255) / 256, 256>>>();
    // 8 warps/block, EPW edges/warp
    int blocks = (NE + 8 * EPW - 1) / (8 * EPW);
    scatter_kernel<<<blocks, 256>>>(edge, recv, send);
    globproj_kernel<<<NG, FD>>>(glob, Wg, bias);
    gemm_kernel<<<(NN + 127) / 128, 256>>>(node, Wn, Wi, Wo, gidx, out);
}

// round 8
// speedup vs baseline: 1.0611x; 1.0602x over previous
#include <cuda_runtime.h>
#include <cuda_bf16.h>
#include <cstdint>

#define NN 100000
#define NE 1600000
#define NG 50
#define FD 128

// Scratch (allocation-free rule: __device__ globals)
__device__ float g_agg_in[(size_t)NN * FD];
__device__ float g_agg_out[(size_t)NN * FD];
__device__ float g_gp[NG * FD];
// Pre-split weights (bf16 hi/lo), layout [n=128][k=384] (k: Wn|Wi|Wo)
__device__ __nv_bfloat16 g_Bhi[FD * 3 * FD];
__device__ __nv_bfloat16 g_Blo[FD * 3 * FD];

// ---------------------------------------------------------------------------
__device__ __forceinline__ uint32_t smem_u32(const void* p) {
    uint32_t a;
    asm("{ .reg .u64 t; cvta.to.shared.u64 t, %1; cvt.u32.u64 %0, t; }"
        : "=r"(a) : "l"(p));
    return a;
}
__device__ __forceinline__ uint32_t pack_bf16(float x, float y) {
    __nv_bfloat162 t = __floats2bfloat162_rn(x, y);   // .x = low half
    return *(uint32_t*)&t;
}

// ---------------------------------------------------------------------------
// Zero the aggregation buffers (102 MB of writes)
// ---------------------------------------------------------------------------
__global__ void zero_kernel() {
    size_t i = (size_t)blockIdx.x * blockDim.x + threadIdx.x;
    size_t n4 = (size_t)NN * FD / 4;
    if (i < n4) {
        ((float4*)g_agg_in)[i]  = make_float4(0.f, 0.f, 0.f, 0.f);
        ((float4*)g_agg_out)[i] = make_float4(0.f, 0.f, 0.f, 0.f);
    }
}

// ---------------------------------------------------------------------------
// Scatter (known-good from R2/R3: LTS-bound, TMA bulk reduce path)
// ---------------------------------------------------------------------------
#define EPW 4

__global__ void __launch_bounds__(256)
scatter_kernel(const float* __restrict__ ef,
               const int* __restrict__ recv,
               const int* __restrict__ send) {
    __shared__ __align__(16) float buf[8][2][FD];
    const int warp = threadIdx.x >> 5;
    const int lane = threadIdx.x & 31;
    const long long ebase = ((long long)blockIdx.x * 8 + warp) * EPW;

    uint32_t sslot[2];
    sslot[0] = smem_u32(&buf[warp][0][0]);
    sslot[1] = smem_u32(&buf[warp][1][0]);

    #pragma unroll
    for (int i = 0; i < EPW; i++) {
        long long e = ebase + i;
        if (e >= NE) break;
        const int slot = i & 1;
        if (i >= 2) {
            if (lane == 0)
                asm volatile("cp.async.bulk.wait_group.read 1;" ::: "memory");
            __syncwarp();
        }
        float4 v = ((const float4*)(ef + (size_t)e * FD))[lane];
        ((float4*)&buf[warp][slot][0])[lane] = v;
        __syncwarp();
        if (lane == 0) {
            const int r = __ldg(recv + e);
            const int s = __ldg(send + e);
            float* pin  = g_agg_in  + (size_t)r * FD;
            float* pout = g_agg_out + (size_t)s * FD;
            asm volatile("fence.proxy.async.shared::cta;" ::: "memory");
            asm volatile(
                "cp.reduce.async.bulk.global.shared::cta.bulk_group.add.f32 "
                "[%0], [%1], %2;"
                :: "l"(pin), "r"(sslot[slot]), "n"(FD * 4) : "memory");
            asm volatile(
                "cp.reduce.async.bulk.global.shared::cta.bulk_group.add.f32 "
                "[%0], [%1], %2;"
                :: "l"(pout), "r"(sslot[slot]), "n"(FD * 4) : "memory");
            asm volatile("cp.async.bulk.commit_group;" ::: "memory");
        }
    }
    if (lane == 0)
        asm volatile("cp.async.bulk.wait_group 0;" ::: "memory");
}

// ---------------------------------------------------------------------------
// gp[g][n] = bias[n] + sum_k glob[g][k] * Wg[n][k]
// ---------------------------------------------------------------------------
__global__ void globproj_kernel(const float* __restrict__ gf,
                                const float* __restrict__ Wg,
                                const float* __restrict__ bias) {
    __shared__ float gs[FD];
    int g = blockIdx.x;
    int n = threadIdx.x;
    gs[n] = gf[g * FD + n];
    __syncthreads();
    float acc = __ldg(bias + n);
    const float* wrow = Wg + (size_t)n * FD;
    #pragma unroll 8
    for (int k = 0; k < FD; k++) acc = fmaf(gs[k], __ldg(wrow + k), acc);
    g_gp[g * FD + n] = acc;
}

// ---------------------------------------------------------------------------
// Pre-split weights into bf16 hi/lo scratch, layout [n][384]
// ---------------------------------------------------------------------------
__global__ void b_split_kernel(const float* __restrict__ Wn,
                               const float* __restrict__ Wi,
                               const float* __restrict__ Wo) {
    int idx = blockIdx.x * blockDim.x + threadIdx.x;   // 128*384 = 49152
    if (idx >= FD * 3 * FD) return;
    int n = idx / (3 * FD);
    int k = idx % (3 * FD);
    int seg = k >> 7, kk = k & 127;
    const float* W = (seg == 0) ? Wn : (seg == 1) ? Wi : Wo;
    float x = W[n * FD + kk];
    __nv_bfloat16 h = __float2bfloat16_rn(x);
    float hf = __bfloat162float(h);
    g_Bhi[idx] = h;
    g_Blo[idx] = __float2bfloat16_rn(x - hf);
}

// ---------------------------------------------------------------------------
// GEMM via mma.sync.m16n8k16 bf16 with 2-term split compensation:
//   out = Ahi*Bhi + Ahi*Blo + Alo*Bhi  (fp32 accumulate, err ~2^-17)
// CTA tile 128x128, 8 warps in 4(m) x 2(n), warp tile 32x64.
// K=384 in 12 chunks of 32 (2 k16 steps each).
// FIX vs R6: A loads use SEGMENT-LOCAL k (kloc), B loads use concatenated
// k (kglob) — the X buffers are separate [NN][128] arrays.
// ---------------------------------------------------------------------------
#define KP 40   // padded k-stride in bf16 elements

#define MMA_BF16(acc, a0, a1, a2, a3, b0, b1)                               \
    asm volatile(                                                           \
        "mma.sync.aligned.m16n8k16.row.col.f32.bf16.bf16.f32 "              \
        "{%0,%1,%2,%3}, {%4,%5,%6,%7}, {%8,%9}, {%0,%1,%2,%3};"             \
        : "+f"(acc[0]), "+f"(acc[1]), "+f"(acc[2]), "+f"(acc[3])            \
        : "r"(a0), "r"(a1), "r"(a2), "r"(a3), "r"(b0), "r"(b1))

__global__ void __launch_bounds__(256, 2)
gemm_mma_kernel(const float* __restrict__ node,
                const int* __restrict__ gidx,
                float* __restrict__ out) {
    __shared__ __align__(16) __nv_bfloat16 As_hi[128][KP];
    __shared__ __align__(16) __nv_bfloat16 As_lo[128][KP];
    __shared__ __align__(16) __nv_bfloat16 Bs_hi[128][KP];
    __shared__ __align__(16) __nv_bfloat16 Bs_lo[128][KP];

    const int tid    = threadIdx.x;
    const int wid    = tid >> 5;
    const int lane   = tid & 31;
    const int gid    = lane >> 2;      // 0..7
    const int t2     = (lane & 3) * 2; // 0,2,4,6
    const int warp_m = (wid & 3) * 32;
    const int warp_n = (wid >> 2) * 64;
    const int m0     = blockIdx.x * 128;

    // A staging: 2 threads per row, 16 k-elements each
    const int arow  = tid >> 1;
    const int ahalf = tid & 1;
    const int gm    = m0 + arow;

    float acc[16][4];
    #pragma unroll
    for (int i = 0; i < 16; i++)
        #pragma unroll
        for (int j = 0; j < 4; j++) acc[i][j] = 0.f;

    #pragma unroll 1
    for (int kb = 0; kb < 12; kb++) {
        const int seg   = kb >> 2;
        const int kloc  = (kb & 3) * 32;       // k within this segment's X buffer
        const int kglob = seg * FD + kloc;     // k within concatenated B scratch
        const float* X  = (seg == 0) ? node : (seg == 1) ? g_agg_in : g_agg_out;

        // ---- B chunk via cp.async (pre-split bf16 hi/lo; concatenated k) ----
        #pragma unroll
        for (int i = 0; i < 2; i++) {
            int c = tid * 2 + i;            // 0..511
            int row = c >> 2, sub = c & 3;  // sub: 16B granule (8 bf16)
            const __nv_bfloat16* sh = g_Bhi + (size_t)row * (3 * FD) + kglob + sub * 8;
            const __nv_bfloat16* sl = g_Blo + (size_t)row * (3 * FD) + kglob + sub * 8;
            asm volatile("cp.async.cg.shared.global [%0], [%1], 16;"
                         :: "r"(smem_u32(&Bs_hi[row][sub * 8])), "l"(sh) : "memory");
            asm volatile("cp.async.cg.shared.global [%0], [%1], 16;"
                         :: "r"(smem_u32(&Bs_lo[row][sub * 8])), "l"(sl) : "memory");
        }
        asm volatile("cp.async.commit_group;" ::: "memory");

        // ---- A chunk: LDG fp32 (segment-LOCAL k), split hi/lo, STS ----
        float4 v[4];
        #pragma unroll
        for (int j = 0; j < 4; j++) {
            if (gm < NN)
                v[j] = *(const float4*)(X + (size_t)gm * FD + kloc + ahalf * 16 + j * 4);
            else
                v[j] = make_float4(0.f, 0.f, 0.f, 0.f);
        }
        uint32_t hw[8], lw[8];
        #pragma unroll
        for (int j = 0; j < 4; j++) {
            float f[4] = {v[j].x, v[j].y, v[j].z, v[j].w};
            float hf[4];
            #pragma unroll
            for (int q = 0; q < 4; q++)
                hf[q] = __bfloat162float(__float2bfloat16_rn(f[q]));
            hw[j * 2 + 0] = pack_bf16(hf[0], hf[1]);
            hw[j * 2 + 1] = pack_bf16(hf[2], hf[3]);
            lw[j * 2 + 0] = pack_bf16(f[0] - hf[0], f[1] - hf[1]);
            lw[j * 2 + 1] = pack_bf16(f[2] - hf[2], f[3] - hf[3]);
        }
        *(uint4*)&As_hi[arow][ahalf * 16]     = make_uint4(hw[0], hw[1], hw[2], hw[3]);
        *(uint4*)&As_hi[arow][ahalf * 16 + 8] = make_uint4(hw[4], hw[5], hw[6], hw[7]);
        *(uint4*)&As_lo[arow][ahalf * 16]     = make_uint4(lw[0], lw[1], lw[2], lw[3]);
        *(uint4*)&As_lo[arow][ahalf * 16 + 8] = make_uint4(lw[4], lw[5], lw[6], lw[7]);

        asm volatile("cp.async.wait_group 0;" ::: "memory");
        __syncthreads();

        // ---- compute: 2 k16 steps ----
        #pragma unroll
        for (int ks = 0; ks < 2; ks++) {
            const int kofs = ks * 16 + t2;
            uint32_t ahi[2][4], alo[2][4];
            #pragma unroll
            for (int ma = 0; ma < 2; ma++) {
                const int r = warp_m + ma * 16 + gid;
                ahi[ma][0] = *(const uint32_t*)&As_hi[r][kofs];
                ahi[ma][1] = *(const uint32_t*)&As_hi[r + 8][kofs];
                ahi[ma][2] = *(const uint32_t*)&As_hi[r][kofs + 8];
                ahi[ma][3] = *(const uint32_t*)&As_hi[r + 8][kofs + 8];
                alo[ma][0] = *(const uint32_t*)&As_lo[r][kofs];
                alo[ma][1] = *(const uint32_t*)&As_lo[r + 8][kofs];
                alo[ma][2] = *(const uint32_t*)&As_lo[r][kofs + 8];
                alo[ma][3] = *(const uint32_t*)&As_lo[r + 8][kofs + 8];
            }
            #pragma unroll
            for (int na = 0; na < 8; na++) {
                const int bn = warp_n + na * 8 + gid;
                uint32_t bhi0 = *(const uint32_t*)&Bs_hi[bn][kofs];
                uint32_t bhi1 = *(const uint32_t*)&Bs_hi[bn][kofs + 8];
                uint32_t blo0 = *(const uint32_t*)&Bs_lo[bn][kofs];
                uint32_t blo1 = *(const uint32_t*)&Bs_lo[bn][kofs + 8];
                #pragma unroll
                for (int ma = 0; ma < 2; ma++) {
                    float* a = acc[ma * 8 + na];
                    MMA_BF16(a, ahi[ma][0], ahi[ma][1], ahi[ma][2], ahi[ma][3], bhi0, bhi1);
                    MMA_BF16(a, ahi[ma][0], ahi[ma][1], ahi[ma][2], ahi[ma][3], blo0, blo1);
                    MMA_BF16(a, alo[ma][0], alo[ma][1], alo[ma][2], alo[ma][3], bhi0, bhi1);
                }
            }
        }
        __syncthreads();   // before next chunk overwrites smem
    }

    // ---- epilogue: + gp[graph_idx[m]] (bias folded), store ----
    #pragma unroll
    for (int ma = 0; ma < 2; ma++) {
        const int mr0 = m0 + warp_m + ma * 16 + gid;       // rows gid, gid+8
        const int mr1 = mr0 + 8;
        const int g0 = (mr0 < NN) ? __ldg(gidx + mr0) : 0;
        const int g1 = (mr1 < NN) ? __ldg(gidx + mr1) : 0;
        #pragma unroll
        for (int na = 0; na < 8; na++) {
            const int n = warp_n + na * 8 + t2;
            const float* a = acc[ma * 8 + na];
            if (mr0 < NN) {
                float2 b = *(const float2*)(g_gp + (size_t)g0 * FD + n);
                *(float2*)(out + (size_t)mr0 * FD + n) =
                    make_float2(a[0] + b.x, a[1] + b.y);
            }
            if (mr1 < NN) {
                float2 b = *(const float2*)(g_gp + (size_t)g1 * FD + n);
                *(float2*)(out + (size_t)mr1 * FD + n) =
                    make_float2(a[2] + b.x, a[3] + b.y);
            }
        }
    }
}

// ---------------------------------------------------------------------------
extern "C" void kernel_launch(void* const* d_in, const int* in_sizes, int n_in,
                              void* d_out, int out_size) {
    const float* node = (const float*)d_in[0];
    const float* edge = (const float*)d_in[1];
    const float* glob = (const float*)d_in[2];
    const float* Wn   = (const float*)d_in[3];
    const float* Wi   = (const float*)d_in[4];
    const float* Wo   = (const float*)d_in[5];
    const float* Wg   = (const float*)d_in[6];
    const float* bias = (const float*)d_in[7];
    const int* recv   = (const int*)d_in[8];
    const int* send   = (const int*)d_in[9];
    const int* gidx   = (const int*)d_in[10];
    float* out        = (float*)d_out;

    zero_kernel<<<((size_t)NN * FD / 4 + 255) / 256, 256>>>();
    int blocks = (NE + 8 * EPW - 1) / (8 * EPW);
    scatter_kernel<<<blocks, 256>>>(edge, recv, send);
    b_split_kernel<<<(FD * 3 * FD + 255) / 256, 256>>>(Wn, Wi, Wo);
    globproj_kernel<<<NG, FD>>>(glob, Wg, bias);
    gemm_mma_kernel<<<(NN + 127) / 128, 256>>>(node, gidx, out);
}

// round 9
// speedup vs baseline: 1.1354x; 1.0701x over previous
#include <cuda_runtime.h>
#include <cuda_bf16.h>
#include <cstdint>

#define NN 100000
#define NE 1600000
#define NG 50
#define FD 128

// Scratch (allocation-free rule: __device__ globals)
__device__ float g_agg_in[(size_t)NN * FD];
__device__ float g_agg_out[(size_t)NN * FD];
__device__ float g_gp[NG * FD];
__device__ __nv_bfloat16 g_Bhi[FD * 3 * FD];
__device__ __nv_bfloat16 g_Blo[FD * 3 * FD];
// CSR binning scratch
__device__ int g_cnt_in[NN],  g_cnt_out[NN];
__device__ int g_off_in[NN],  g_off_out[NN];
__device__ int g_cur_in[NN],  g_cur_out[NN];
__device__ int g_bin_in[NE],  g_bin_out[NE];

// ---------------------------------------------------------------------------
__device__ __forceinline__ uint32_t smem_u32(const void* p) {
    uint32_t a;
    asm("{ .reg .u64 t; cvta.to.shared.u64 t, %1; cvt.u32.u64 %0, t; }"
        : "=r"(a) : "l"(p));
    return a;
}
__device__ __forceinline__ uint32_t pack_bf16(float x, float y) {
    __nv_bfloat162 t = __floats2bfloat162_rn(x, y);
    return *(uint32_t*)&t;
}

// ---------------------------------------------------------------------------
// CSR build: zero counts -> histogram -> exclusive scan -> fill bins
// ---------------------------------------------------------------------------
__global__ void init_counts_kernel() {
    int i = blockIdx.x * blockDim.x + threadIdx.x;
    if (i < NN) { g_cnt_in[i] = 0; g_cnt_out[i] = 0; }
}

__global__ void hist_kernel(const int* __restrict__ recv,
                            const int* __restrict__ send) {
    int e = blockIdx.x * blockDim.x + threadIdx.x;
    if (e < NE) {
        atomicAdd(&g_cnt_in[recv[e]], 1);
        atomicAdd(&g_cnt_out[send[e]], 1);
    }
}

// one block per array (grid=2), 1024 threads, 98 elems/thread
#define SCAN_C 98
__global__ void scan_kernel() {
    const int* cnt = blockIdx.x ? g_cnt_out : g_cnt_in;
    int* off = blockIdx.x ? g_off_out : g_off_in;
    int* cur = blockIdx.x ? g_cur_out : g_cur_in;
    const int tid = threadIdx.x;
    const int base = tid * SCAN_C;
    int s = 0;
    #pragma unroll 7
    for (int i = 0; i < SCAN_C; i++) {
        int idx = base + i;
        if (idx < NN) s += cnt[idx];
    }
    __shared__ int sh[1024];
    sh[tid] = s;
    __syncthreads();
    for (int o = 1; o < 1024; o <<= 1) {
        int v = (tid >= o) ? sh[tid - o] : 0;
        __syncthreads();
        sh[tid] += v;
        __syncthreads();
    }
    int run = sh[tid] - s;   // exclusive prefix
    for (int i = 0; i < SCAN_C; i++) {
        int idx = base + i;
        if (idx < NN) {
            off[idx] = run;
            cur[idx] = run;
            run += cnt[idx];
        }
    }
}

__global__ void fill_kernel(const int* __restrict__ recv,
                            const int* __restrict__ send) {
    int e = blockIdx.x * blockDim.x + threadIdx.x;
    if (e < NE) {
        int p = atomicAdd(&g_cur_in[recv[e]], 1);
        g_bin_in[p] = e;
        int q = atomicAdd(&g_cur_out[send[e]], 1);
        g_bin_out[q] = e;
    }
}

// ---------------------------------------------------------------------------
// Gather: one warp per node per direction (grid.y = 0:in, 1:out).
// Each lane owns 16B of the 512B feature row; unroll-4 for MLP.
// Writes agg directly (no zero pass needed).
// ---------------------------------------------------------------------------
__global__ void __launch_bounds__(256)
gather_kernel(const float* __restrict__ ef) {
    const int warp = threadIdx.x >> 5;
    const int lane = threadIdx.x & 31;
    const int node = blockIdx.x * 8 + warp;
    if (node >= NN) return;
    const int* off; const int* cnt; const int* bin; float* agg;
    if (blockIdx.y == 0) { off = g_off_in;  cnt = g_cnt_in;  bin = g_bin_in;  agg = g_agg_in; }
    else                 { off = g_off_out; cnt = g_cnt_out; bin = g_bin_out; agg = g_agg_out; }

    const int start = __ldg(off + node);
    const int end   = start + __ldg(cnt + node);
    const float4* ef4 = (const float4*)ef;
    float4 acc = make_float4(0.f, 0.f, 0.f, 0.f);

    int j = start;
    for (; j + 4 <= end; j += 4) {
        int i0 = __ldg(bin + j), i1 = __ldg(bin + j + 1);
        int i2 = __ldg(bin + j + 2), i3 = __ldg(bin + j + 3);
        float4 v0 = __ldg(ef4 + (size_t)i0 * 32 + lane);
        float4 v1 = __ldg(ef4 + (size_t)i1 * 32 + lane);
        float4 v2 = __ldg(ef4 + (size_t)i2 * 32 + lane);
        float4 v3 = __ldg(ef4 + (size_t)i3 * 32 + lane);
        acc.x += (v0.x + v1.x) + (v2.x + v3.x);
        acc.y += (v0.y + v1.y) + (v2.y + v3.y);
        acc.z += (v0.z + v1.z) + (v2.z + v3.z);
        acc.w += (v0.w + v1.w) + (v2.w + v3.w);
    }
    for (; j < end; j++) {
        int i0 = __ldg(bin + j);
        float4 v = __ldg(ef4 + (size_t)i0 * 32 + lane);
        acc.x += v.x; acc.y += v.y; acc.z += v.z; acc.w += v.w;
    }
    ((float4*)(agg + (size_t)node * FD))[lane] = acc;
}

// ---------------------------------------------------------------------------
// gp[g][n] = bias[n] + glob[g] . Wg[n]   — warp per output, shfl reduce
// ---------------------------------------------------------------------------
__global__ void __launch_bounds__(256)
globproj_kernel(const float* __restrict__ gf,
                const float* __restrict__ Wg,
                const float* __restrict__ bias) {
    const int warp = threadIdx.x >> 5;
    const int lane = threadIdx.x & 31;
    const int idx = blockIdx.x * 8 + warp;      // 0..NG*FD-1
    if (idx >= NG * FD) return;
    const int g = idx >> 7, n = idx & 127;
    const float* gr = gf + (size_t)g * FD;
    const float* wr = Wg + (size_t)n * FD;
    float s = 0.f;
    #pragma unroll
    for (int q = 0; q < 4; q++)
        s += __ldg(gr + lane + q * 32) * __ldg(wr + lane + q * 32);
    #pragma unroll
    for (int o = 16; o > 0; o >>= 1) s += __shfl_xor_sync(0xFFFFFFFFu, s, o);
    if (lane == 0) g_gp[idx] = s + __ldg(bias + n);
}

// ---------------------------------------------------------------------------
// Pre-split weights into bf16 hi/lo scratch, layout [n][384]
// ---------------------------------------------------------------------------
__global__ void b_split_kernel(const float* __restrict__ Wn,
                               const float* __restrict__ Wi,
                               const float* __restrict__ Wo) {
    int idx = blockIdx.x * blockDim.x + threadIdx.x;
    if (idx >= FD * 3 * FD) return;
    int n = idx / (3 * FD);
    int k = idx % (3 * FD);
    int seg = k >> 7, kk = k & 127;
    const float* W = (seg == 0) ? Wn : (seg == 1) ? Wi : Wo;
    float x = W[n * FD + kk];
    __nv_bfloat16 h = __float2bfloat16_rn(x);
    float hf = __bfloat162float(h);
    g_Bhi[idx] = h;
    g_Blo[idx] = __float2bfloat16_rn(x - hf);
}

// ---------------------------------------------------------------------------
// GEMM via mma.sync.m16n8k16 bf16, 2-term split compensation (R8, passing)
// ---------------------------------------------------------------------------
#define KP 40

#define MMA_BF16(acc, a0, a1, a2, a3, b0, b1)                               \
    asm volatile(                                                           \
        "mma.sync.aligned.m16n8k16.row.col.f32.bf16.bf16.f32 "              \
        "{%0,%1,%2,%3}, {%4,%5,%6,%7}, {%8,%9}, {%0,%1,%2,%3};"             \
        : "+f"(acc[0]), "+f"(acc[1]), "+f"(acc[2]), "+f"(acc[3])            \
        : "r"(a0), "r"(a1), "r"(a2), "r"(a3), "r"(b0), "r"(b1))

__global__ void __launch_bounds__(256, 2)
gemm_mma_kernel(const float* __restrict__ node,
                const int* __restrict__ gidx,
                float* __restrict__ out) {
    __shared__ __align__(16) __nv_bfloat16 As_hi[128][KP];
    __shared__ __align__(16) __nv_bfloat16 As_lo[128][KP];
    __shared__ __align__(16) __nv_bfloat16 Bs_hi[128][KP];
    __shared__ __align__(16) __nv_bfloat16 Bs_lo[128][KP];

    const int tid    = threadIdx.x;
    const int wid    = tid >> 5;
    const int lane   = tid & 31;
    const int gid    = lane >> 2;
    const int t2     = (lane & 3) * 2;
    const int warp_m = (wid & 3) * 32;
    const int warp_n = (wid >> 2) * 64;
    const int m0     = blockIdx.x * 128;

    const int arow  = tid >> 1;
    const int ahalf = tid & 1;
    const int gm    = m0 + arow;

    float acc[16][4];
    #pragma unroll
    for (int i = 0; i < 16; i++)
        #pragma unroll
        for (int j = 0; j < 4; j++) acc[i][j] = 0.f;

    #pragma unroll 1
    for (int kb = 0; kb < 12; kb++) {
        const int seg   = kb >> 2;
        const int kloc  = (kb & 3) * 32;
        const int kglob = seg * FD + kloc;
        const float* X  = (seg == 0) ? node : (seg == 1) ? g_agg_in : g_agg_out;

        #pragma unroll
        for (int i = 0; i < 2; i++) {
            int c = tid * 2 + i;
            int row = c >> 2, sub = c & 3;
            const __nv_bfloat16* sh = g_Bhi + (size_t)row * (3 * FD) + kglob + sub * 8;
            const __nv_bfloat16* sl = g_Blo + (size_t)row * (3 * FD) + kglob + sub * 8;
            asm volatile("cp.async.cg.shared.global [%0], [%1], 16;"
                         :: "r"(smem_u32(&Bs_hi[row][sub * 8])), "l"(sh) : "memory");
            asm volatile("cp.async.cg.shared.global [%0], [%1], 16;"
                         :: "r"(smem_u32(&Bs_lo[row][sub * 8])), "l"(sl) : "memory");
        }
        asm volatile("cp.async.commit_group;" ::: "memory");

        float4 v[4];
        #pragma unroll
        for (int j = 0; j < 4; j++) {
            if (gm < NN)
                v[j] = *(const float4*)(X + (size_t)gm * FD + kloc + ahalf * 16 + j * 4);
            else
                v[j] = make_float4(0.f, 0.f, 0.f, 0.f);
        }
        uint32_t hw[8], lw[8];
        #pragma unroll
        for (int j = 0; j < 4; j++) {
            float f[4] = {v[j].x, v[j].y, v[j].z, v[j].w};
            float hf[4];
            #pragma unroll
            for (int q = 0; q < 4; q++)
                hf[q] = __bfloat162float(__float2bfloat16_rn(f[q]));
            hw[j * 2 + 0] = pack_bf16(hf[0], hf[1]);
            hw[j * 2 + 1] = pack_bf16(hf[2], hf[3]);
            lw[j * 2 + 0] = pack_bf16(f[0] - hf[0], f[1] - hf[1]);
            lw[j * 2 + 1] = pack_bf16(f[2] - hf[2], f[3] - hf[3]);
        }
        *(uint4*)&As_hi[arow][ahalf * 16]     = make_uint4(hw[0], hw[1], hw[2], hw[3]);
        *(uint4*)&As_hi[arow][ahalf * 16 + 8] = make_uint4(hw[4], hw[5], hw[6], hw[7]);
        *(uint4*)&As_lo[arow][ahalf * 16]     = make_uint4(lw[0], lw[1], lw[2], lw[3]);
        *(uint4*)&As_lo[arow][ahalf * 16 + 8] = make_uint4(lw[4], lw[5], lw[6], lw[7]);

        asm volatile("cp.async.wait_group 0;" ::: "memory");
        __syncthreads();

        #pragma unroll
        for (int ks = 0; ks < 2; ks++) {
            const int kofs = ks * 16 + t2;
            uint32_t ahi[2][4], alo[2][4];
            #pragma unroll
            for (int ma = 0; ma < 2; ma++) {
                const int r = warp_m + ma * 16 + gid;
                ahi[ma][0] = *(const uint32_t*)&As_hi[r][kofs];
                ahi[ma][1] = *(const uint32_t*)&As_hi[r + 8][kofs];
                ahi[ma][2] = *(const uint32_t*)&As_hi[r][kofs + 8];
                ahi[ma][3] = *(const uint32_t*)&As_hi[r + 8][kofs + 8];
                alo[ma][0] = *(const uint32_t*)&As_lo[r][kofs];
                alo[ma][1] = *(const uint32_t*)&As_lo[r + 8][kofs];
                alo[ma][2] = *(const uint32_t*)&As_lo[r][kofs + 8];
                alo[ma][3] = *(const uint32_t*)&As_lo[r + 8][kofs + 8];
            }
            #pragma unroll
            for (int na = 0; na < 8; na++) {
                const int bn = warp_n + na * 8 + gid;
                uint32_t bhi0 = *(const uint32_t*)&Bs_hi[bn][kofs];
                uint32_t bhi1 = *(const uint32_t*)&Bs_hi[bn][kofs + 8];
                uint32_t blo0 = *(const uint32_t*)&Bs_lo[bn][kofs];
                uint32_t blo1 = *(const uint32_t*)&Bs_lo[bn][kofs + 8];
                #pragma unroll
                for (int ma = 0; ma < 2; ma++) {
                    float* a = acc[ma * 8 + na];
                    MMA_BF16(a, ahi[ma][0], ahi[ma][1], ahi[ma][2], ahi[ma][3], bhi0, bhi1);
                    MMA_BF16(a, ahi[ma][0], ahi[ma][1], ahi[ma][2], ahi[ma][3], blo0, blo1);
                    MMA_BF16(a, alo[ma][0], alo[ma][1], alo[ma][2], alo[ma][3], bhi0, bhi1);
                }
            }
        }
        __syncthreads();
    }

    #pragma unroll
    for (int ma = 0; ma < 2; ma++) {
        const int mr0 = m0 + warp_m + ma * 16 + gid;
        const int mr1 = mr0 + 8;
        const int g0 = (mr0 < NN) ? __ldg(gidx + mr0) : 0;
        const int g1 = (mr1 < NN) ? __ldg(gidx + mr1) : 0;
        #pragma unroll
        for (int na = 0; na < 8; na++) {
            const int n = warp_n + na * 8 + t2;
            const float* a = acc[ma * 8 + na];
            if (mr0 < NN) {
                float2 b = *(const float2*)(g_gp + (size_t)g0 * FD + n);
                *(float2*)(out + (size_t)mr0 * FD + n) =
                    make_float2(a[0] + b.x, a[1] + b.y);
            }
            if (mr1 < NN) {
                float2 b = *(const float2*)(g_gp + (size_t)g1 * FD + n);
                *(float2*)(out + (size_t)mr1 * FD + n) =
                    make_float2(a[2] + b.x, a[3] + b.y);
            }
        }
    }
}

// ---------------------------------------------------------------------------
extern "C" void kernel_launch(void* const* d_in, const int* in_sizes, int n_in,
                              void* d_out, int out_size) {
    const float* node = (const float*)d_in[0];
    const float* edge = (const float*)d_in[1];
    const float* glob = (const float*)d_in[2];
    const float* Wn   = (const float*)d_in[3];
    const float* Wi   = (const float*)d_in[4];
    const float* Wo   = (const float*)d_in[5];
    const float* Wg   = (const float*)d_in[6];
    const float* bias = (const float*)d_in[7];
    const int* recv   = (const int*)d_in[8];
    const int* send   = (const int*)d_in[9];
    const int* gidx   = (const int*)d_in[10];
    float* out        = (float*)d_out;

    // CSR build
    init_counts_kernel<<<(NN + 255) / 256, 256>>>();
    hist_kernel<<<(NE + 255) / 256, 256>>>(recv, send);
    scan_kernel<<<2, 1024>>>();
    fill_kernel<<<(NE + 255) / 256, 256>>>(recv, send);
    // aggregate via gather (no zeroing needed)
    dim3 ggrid((NN + 7) / 8, 2);
    gather_kernel<<<ggrid, 256>>>(edge);
    // small preps
    b_split_kernel<<<(FD * 3 * FD + 255) / 256, 256>>>(Wn, Wi, Wo);
    globproj_kernel<<<(NG * FD + 7) / 8, 256>>>(glob, Wg, bias);
    // fused projection GEMM
    gemm_mma_kernel<<<(NN + 127) / 128, 256>>>(node, gidx, out);
}